// round 16
// baseline (speedup 1.0000x reference)
#include <cuda_runtime.h>
#include <cstdint>

// Shapes (fixed): predicted/target [32,4,512,512] f32; tokens unused;
// text_positions [32,64,2] f32. Output: 1 f32 scalar.
//
// result = [ sum(d^2) + 3 * sum_{masked px} d^2 ] / N,  d = p - t
//
// R10: per-thread cp.async (LDGSTS) 3-stage pipeline. Each thread stages its
// own 16B slots in SMEM and waits with cp.async.wait_group (private
// scoreboard; NO block barriers — R9's mbarrier-per-8KB tax is gone).
// In-flight bytes are SMEM-depth-bounded, not register-bounded (the cap that
// pinned every LDG variant at <=74% DRAM). Paint / sparse fixup / fold
// carried from R8 (proven, rel_err 1.11e-7).

#define NB 32
#define NC 4
#define NH 512
#define NW 512
#define NT 64
#define BOX 5

#define WORDS_PER_ROW   16
#define WORDS_PER_BATCH 8192
#define MASK_WORDS      262144        // 1 MB bitfield
#define N_ELEMS         33554432
#define N4              8388608       // float4 pairs

#define GRID     1184                 // 148 SMs * 8 CTAs
#define THREADS  256
#define PAINT_CTAS 64

#define D        3                    // pipeline depth (stages)
#define STRIDE   (GRID * THREADS)     // 303104
#define NMAX     28                   // ceil(N4 / STRIDE)

__device__ unsigned g_mask[MASK_WORDS];
__device__ float    g_partials[GRID];
__device__ unsigned g_count = 0;                 // wraps via atomicInc
__device__ volatile unsigned g_paint_done = 0;   // reset by last block

struct __align__(16) Smem {
    float4 pbuf[D][THREADS];          // 12 KB
    float4 qbuf[D][THREADS];          // 12 KB
    float  sx[NT], sy[NT];
    float  ssum[THREADS / 32];
    double dsum[THREADS / 32];
    int    s_last;
};

__device__ __forceinline__ unsigned smem_u32(const void* p) {
    return (unsigned)__cvta_generic_to_shared(p);
}
__device__ __forceinline__ void cp16(unsigned dst, const void* src) {
    asm volatile("cp.async.cg.shared.global [%0], [%1], 16;"
                 :: "r"(dst), "l"(src) : "memory");
}
__device__ __forceinline__ void cp_commit() {
    asm volatile("cp.async.commit_group;" ::: "memory");
}
__device__ __forceinline__ void cp_wait2() {
    asm volatile("cp.async.wait_group 2;" ::: "memory");
}

__global__ void __launch_bounds__(THREADS)
fused_loss_kernel(const float4* __restrict__ p4,
                  const float4* __restrict__ q4,
                  const float*  __restrict__ pf,
                  const float*  __restrict__ qf,
                  const float*  __restrict__ pos,
                  float* __restrict__ out) {
    __shared__ Smem sm;
    const int tid = threadIdx.x;
    const int bid = blockIdx.x;

    // ---- paint (CTAs 0..63, cold path; low bids -> scheduled first) ----
    if (bid < PAINT_CTAS) {
        const int batch = bid >> 1;
        const int row   = ((bid & 1) << 8) + tid;
        if (tid < NT * 2) {
            float v = pos[(batch * NT) * 2 + tid];
            if (tid & 1) sm.sy[tid >> 1] = v; else sm.sx[tid >> 1] = v;
        }
        __syncthreads();
        unsigned w[WORDS_PER_ROW];
        #pragma unroll
        for (int k = 0; k < WORDS_PER_ROW; k++) w[k] = 0u;
        for (int t = 0; t < NT; t++) {
            float x = sm.sx[t], y = sm.sy[t];
            if (!(x > 0.0f && y > 0.0f)) continue;
            int yp = (int)floorf(y * (float)NH);
            if (row < yp - BOX || row >= yp + BOX) continue;
            int xp = (int)floorf(x * (float)NW);
            int x0 = max(xp - BOX, 0);
            int x1 = min(xp + BOX, NW);
            if (x0 >= x1) continue;
            int w0 = x0 >> 5, w1 = (x1 - 1) >> 5;
            if (w0 == w1) {
                w[w0] |= ((1u << (x1 - x0)) - 1u) << (x0 & 31);  // width<=10<32
            } else {
                w[w0] |= ~0u << (x0 & 31);
                w[w1] |= (1u << (x1 - (w1 << 5))) - 1u;          // 1..9 bits
            }
        }
        uint4* dst = (uint4*)&g_mask[batch * WORDS_PER_BATCH + row * WORDS_PER_ROW];
        #pragma unroll
        for (int k = 0; k < 4; k++)
            dst[k] = make_uint4(w[4*k], w[4*k+1], w[4*k+2], w[4*k+3]);
        __syncthreads();
        if (tid == 0) {
            __threadfence();
            atomicAdd((unsigned*)&g_paint_done, 1u);
        }
    }

    // ---- Phase A: per-thread cp.async 3-stage pipeline, sum(d^2) ----
    const unsigned pb = smem_u32(&sm.pbuf[0][tid]);
    const unsigned qb = smem_u32(&sm.qbuf[0][tid]);
    const int gi = bid * THREADS + tid;          // k=0 index; always < N4

    // prologue: groups for k=0 (slot 0) and k=1 (slot 1); both always in range
    cp16(pb,          p4 + gi);
    cp16(qb,          q4 + gi);
    cp_commit();
    cp16(pb + 4096,   p4 + gi + STRIDE);
    cp16(qb + 4096,   q4 + gi + STRIDE);
    cp_commit();

    float sum = 0.0f;
    int icons = gi;                    // consume index (k)
    int ipre  = gi + 2 * STRIDE;       // prefetch index (k+2)
    int cslot = 0, pslot = 2;
    for (int k = 0; k < NMAX; k++) {
        if (ipre < N4) {
            cp16(pb + (pslot << 12), p4 + ipre);
            cp16(qb + (pslot << 12), q4 + ipre);
        }
        cp_commit();                   // unconditional: group accounting stays aligned
        cp_wait2();                    // <=2 outstanding -> group k complete
        if (icons < N4) {
            float4 a = sm.pbuf[cslot][tid];
            float4 b = sm.qbuf[cslot][tid];
            float d0 = a.x - b.x, d1 = a.y - b.y;
            float d2 = a.z - b.z, d3 = a.w - b.w;
            sum = fmaf(d0, d0, sum);
            sum = fmaf(d1, d1, sum);
            sum = fmaf(d2, d2, sum);
            sum = fmaf(d3, d3, sum);
        }
        icons += STRIDE;
        ipre  += STRIDE;
        cslot = (cslot == D - 1) ? 0 : cslot + 1;
        pslot = (pslot == D - 1) ? 0 : pslot + 1;
    }

    // ---- wait for paint (stream >> paint; painters are in wave 1) ----
    while (g_paint_done != PAINT_CTAS) { }
    __threadfence();

    // ---- Phase B: masked fixup, one mask word per thread ----
    {
        const int g = bid * THREADS + tid;
        if (g < MASK_WORDS) {
            unsigned w = g_mask[g];
            if (w) {
                const int batch = g >> 13;
                const int rem   = g & 8191;
                const int row   = rem >> 4;
                const int cbase = (rem & 15) << 5;
                const int base  = (batch << 20) + (row << 9);  // ch0 float idx
                float bsum = 0.0f;
                while (w) {
                    int bit = __ffs(w) - 1;
                    w &= w - 1;
                    int idx = base + cbase + bit;
                    #pragma unroll
                    for (int ch = 0; ch < NC; ch++) {
                        float d = pf[idx + (ch << 18)] - qf[idx + (ch << 18)];
                        bsum = fmaf(d, d, bsum);
                    }
                }
                sum = fmaf(3.0f, bsum, sum);
            }
        }
    }

    // ---- block reduce + last-block fold ----
    #pragma unroll
    for (int o = 16; o > 0; o >>= 1)
        sum += __shfl_xor_sync(0xFFFFFFFFu, sum, o);
    int lane = tid & 31, wid = tid >> 5;
    if (lane == 0) sm.ssum[wid] = sum;
    __syncthreads();
    if (wid == 0) {
        float v = (lane < THREADS / 32) ? sm.ssum[lane] : 0.0f;
        #pragma unroll
        for (int o = 4; o > 0; o >>= 1)
            v += __shfl_xor_sync(0xFFFFFFFFu, v, o);
        if (lane == 0) {
            g_partials[bid] = v;
            __threadfence();
            unsigned prev = atomicInc(&g_count, GRID - 1);
            sm.s_last = (prev == GRID - 1);
        }
    }
    __syncthreads();

    if (sm.s_last) {
        double d = 0.0;
        for (int i = tid; i < GRID; i += THREADS)
            d += (double)g_partials[i];
        #pragma unroll
        for (int o = 16; o > 0; o >>= 1)
            d += __shfl_xor_sync(0xFFFFFFFFu, d, o);
        if (lane == 0) sm.dsum[wid] = d;
        __syncthreads();
        if (wid == 0) {
            double t = (lane < THREADS / 32) ? sm.dsum[lane] : 0.0;
            #pragma unroll
            for (int o = 4; o > 0; o >>= 1)
                t += __shfl_xor_sync(0xFFFFFFFFu, t, o);
            if (lane == 0) {
                out[0] = (float)(t * (1.0 / (double)N_ELEMS));
                g_paint_done = 0;            // reset for next graph replay
                __threadfence();
            }
        }
    }
}

extern "C" void kernel_launch(void* const* d_in, const int* in_sizes, int n_in,
                              void* d_out, int out_size) {
    const float* pred = (const float*)d_in[0];
    const float* targ = (const float*)d_in[1];
    // d_in[2] (text_tokens) unused by the math.
    const float* pos  = (const float*)d_in[3];
    fused_loss_kernel<<<GRID, THREADS>>>((const float4*)pred,
                                         (const float4*)targ,
                                         pred, targ, pos, (float*)d_out);
}

// round 17
// speedup vs baseline: 1.2355x; 1.2355x over previous
#include <cuda_runtime.h>
#include <cstdint>

// Shapes (fixed): predicted/target [32,4,512,512] f32; tokens unused;
// text_positions [32,64,2] f32. Output: 1 f32 scalar.
//
// result = mean over (b,c,h,w) of (1 + 3*mask[b,h,w]) * (p - t)^2
//
// R11: L2 bulk-prefetch pipeline. cp.async.bulk.prefetch.L2.global stages
// each CTA's NEXT 16KB-per-array block into L2 (no dest register, no SMEM,
// no completion tracking) while the proven 32-reg mask-in-loop body consumes
// the CURRENT block as L2 hits. DRAM fetch MLP now lives in the bulk engine,
// decoupled from RF / warps / wait-group depth — the caps that pinned every
// prior variant at <=74% DRAM. Paint fused (CTAs 0..63) + flag; fold fused.

#define NB 32
#define NC 4
#define NH 512
#define NW 512
#define NT 64
#define BOX 5

#define WORDS_PER_ROW   16
#define WORDS_PER_BATCH 8192
#define MASK_WORDS      262144        // 1 MB bitfield
#define N_ELEMS         33554432
#define N4              8388608       // float4 elements per array

#define GRID     1184                 // 148 SMs * 8 CTAs: one full wave
#define THREADS  256
#define PAINT_CTAS 64

#define BLK_F4   1024                 // float4 per array per block = 16 KB
#define BLK_BYTES 16384
#define NBLK     (N4 / BLK_F4)        // 8192

__device__ unsigned g_mask[MASK_WORDS];
__device__ float    g_partials[GRID];
__device__ unsigned g_count = 0;                 // wraps via atomicInc
__device__ volatile unsigned g_paint_done = 0;   // reset by last block

__device__ __forceinline__ void l2_prefetch(const void* p) {
    asm volatile("cp.async.bulk.prefetch.L2.global [%0], %1;"
                 :: "l"(p), "r"(BLK_BYTES) : "memory");
}

__global__ void __launch_bounds__(THREADS)
fused_loss_kernel(const float4* __restrict__ p4,
                  const float4* __restrict__ q4,
                  const float*  __restrict__ pos,
                  float* __restrict__ out) {
    __shared__ float  sx[NT], sy[NT];
    __shared__ float  ssum[THREADS / 32];
    __shared__ double dsum[THREADS / 32];
    __shared__ int    s_last;

    const int tid = threadIdx.x;
    const int bid = blockIdx.x;

    // ---- prologue: prefetch this CTA's first block (warms DRAM->L2 while
    //      paint runs; LDGs on block 0 merge with the in-flight fill) ----
    if (tid == 0 && bid < NBLK) {
        l2_prefetch(p4 + (size_t)bid * BLK_F4);
        l2_prefetch(q4 + (size_t)bid * BLK_F4);
    }

    // ---- paint (CTAs 0..63; cold path; all CTAs co-resident) ----
    if (bid < PAINT_CTAS) {
        const int batch = bid >> 1;
        const int row   = ((bid & 1) << 8) + tid;     // 0..511
        if (tid < NT * 2) {
            float v = pos[(batch * NT) * 2 + tid];
            if (tid & 1) sy[tid >> 1] = v; else sx[tid >> 1] = v;
        }
        __syncthreads();
        unsigned w[WORDS_PER_ROW];
        #pragma unroll
        for (int k = 0; k < WORDS_PER_ROW; k++) w[k] = 0u;
        for (int t = 0; t < NT; t++) {
            float x = sx[t], y = sy[t];
            if (!(x > 0.0f && y > 0.0f)) continue;
            int yp = (int)floorf(y * (float)NH);
            if (row < yp - BOX || row >= yp + BOX) continue;
            int xp = (int)floorf(x * (float)NW);
            int x0 = max(xp - BOX, 0);
            int x1 = min(xp + BOX, NW);
            if (x0 >= x1) continue;
            int w0 = x0 >> 5, w1 = (x1 - 1) >> 5;
            if (w0 == w1) {
                w[w0] |= ((1u << (x1 - x0)) - 1u) << (x0 & 31);  // width<=10<32
            } else {
                w[w0] |= ~0u << (x0 & 31);
                w[w1] |= (1u << (x1 - (w1 << 5))) - 1u;          // 1..9 bits
            }
        }
        uint4* dst = (uint4*)&g_mask[batch * WORDS_PER_BATCH + row * WORDS_PER_ROW];
        #pragma unroll
        for (int k = 0; k < 4; k++)
            dst[k] = make_uint4(w[4*k], w[4*k+1], w[4*k+2], w[4*k+3]);
        __syncthreads();
        if (tid == 0) {
            __threadfence();
            atomicAdd((unsigned*)&g_paint_done, 1u);
        }
    }

    // ---- wait for mask (tid0 spins; painters are low bids, wave-1) ----
    if (tid == 0) {
        while (g_paint_done != PAINT_CTAS) { }
    }
    __syncthreads();
    __threadfence();

    // ---- stream: block-wise over 16KB/array chunks, prefetching next ----
    float sum = 0.0f;
    for (int b = bid; b < NBLK; b += GRID) {
        if (tid == 0) {
            int nb = b + GRID;                      // one-block lead (~5.7us)
            if (nb < NBLK) {
                l2_prefetch(p4 + (size_t)nb * BLK_F4);
                l2_prefetch(q4 + (size_t)nb * BLK_F4);
            }
        }
        const int base = b * BLK_F4;
        #pragma unroll 4
        for (int j = 0; j < BLK_F4 / THREADS; j++) {
            int i = base + (j << 8) + tid;
            float4 a = p4[i];
            float4 v = q4[i];
            unsigned fi = (unsigned)i << 2;
            unsigned word = g_mask[((fi >> 7) & 0xFFFFE000u) | ((fi >> 5) & 0x1FFFu)];
            unsigned bits = word >> ((i & 7) << 2);

            float d0 = a.x - v.x; d0 *= d0;
            float d1 = a.y - v.y; d1 *= d1;
            float d2 = a.z - v.z; d2 *= d2;
            float d3 = a.w - v.w; d3 *= d3;

            float m = (float)(bits & 1u)        * d0
                    + (float)((bits >> 1) & 1u) * d1
                    + (float)((bits >> 2) & 1u) * d2
                    + (float)((bits >> 3) & 1u) * d3;
            sum += (d0 + d1 + d2 + d3) + 3.0f * m;
        }
    }

    // ---- block reduce + last-block fold ----
    #pragma unroll
    for (int o = 16; o > 0; o >>= 1)
        sum += __shfl_xor_sync(0xFFFFFFFFu, sum, o);
    int lane = tid & 31, wid = tid >> 5;
    if (lane == 0) ssum[wid] = sum;
    __syncthreads();
    if (wid == 0) {
        float v = (lane < THREADS / 32) ? ssum[lane] : 0.0f;
        #pragma unroll
        for (int o = 4; o > 0; o >>= 1)
            v += __shfl_xor_sync(0xFFFFFFFFu, v, o);
        if (lane == 0) {
            g_partials[bid] = v;
            __threadfence();
            unsigned prev = atomicInc(&g_count, GRID - 1);   // wraps after last
            s_last = (prev == GRID - 1);
        }
    }
    __syncthreads();

    if (s_last) {
        double d = 0.0;
        for (int i = tid; i < GRID; i += THREADS)
            d += (double)g_partials[i];
        #pragma unroll
        for (int o = 16; o > 0; o >>= 1)
            d += __shfl_xor_sync(0xFFFFFFFFu, d, o);
        if (lane == 0) dsum[wid] = d;
        __syncthreads();
        if (wid == 0) {
            double t = (lane < THREADS / 32) ? dsum[lane] : 0.0;
            #pragma unroll
            for (int o = 4; o > 0; o >>= 1)
                t += __shfl_xor_sync(0xFFFFFFFFu, t, o);
            if (lane == 0) {
                out[0] = (float)(t * (1.0 / (double)N_ELEMS));
                g_paint_done = 0;             // reset for next graph replay
                __threadfence();
            }
        }
    }
}

extern "C" void kernel_launch(void* const* d_in, const int* in_sizes, int n_in,
                              void* d_out, int out_size) {
    const float* pred = (const float*)d_in[0];
    const float* targ = (const float*)d_in[1];
    // d_in[2] (text_tokens) unused by the math.
    const float* pos  = (const float*)d_in[3];
    fused_loss_kernel<<<GRID, THREADS>>>((const float4*)pred,
                                         (const float4*)targ,
                                         pos, (float*)d_out);
}